// round 4
// baseline (speedup 1.0000x reference)
#include <cuda_runtime.h>
#include <math.h>

// ---------------------------------------------------------------------------
// Scratch buffers (device globals -- no allocation inside kernel_launch)
// ---------------------------------------------------------------------------
__device__ __align__(256) float g_bufX[16100000];   // padded input 64*5*258*194
__device__ __align__(256) float g_bufA[6400000];    // unpadded conv outputs
__device__ __align__(256) float g_bufB[6600000];    // padded activations
__device__ __align__(256) float g_bufC[6600000];    // padded activations

// ---------------------------------------------------------------------------
// Zero-pad copy: src (H x W planes) -> dst ((H+2) x (W+2), halo=0)
// ---------------------------------------------------------------------------
__global__ void pad_copy_kernel(const float* __restrict__ src, float* __restrict__ dst,
                                int H, int W, int HP, int WP)
{
    const float* s = src + (size_t)blockIdx.x * H * W;
    float* d = dst + (size_t)blockIdx.x * HP * WP;
    int tot = HP * WP;
    for (int i = threadIdx.x; i < tot; i += blockDim.x) {
        int h = i / WP, w = i % WP;
        bool in = (h >= 1) && (h <= H) && (w >= 1) && (w <= W);
        d[i] = in ? s[(h - 1) * W + (w - 1)] : 0.f;
    }
}

// ---------------------------------------------------------------------------
// Tiled implicit-GEMM conv on PADDED input, vectorized accesses.
// Input taps via LDG.64 (float2); weights via LDS.128 from smem laid out
// [ci][kh][co][kw-pad-4]. Thread computes CO_M x PIX_M = 4x4 outputs.
// ---------------------------------------------------------------------------
template<int K, int S, int CIN, int HP, int WP, int COUT, int HOUT, int WOUT,
         int CO_T, int CI_T, int ZSPLIT, bool ATOMIC, bool BIAS, bool RELU>
__global__ void __launch_bounds__(256)
conv_tiled(const float* __restrict__ in,
           const float* __restrict__ w,
           const float* __restrict__ bias,
           float* __restrict__ out)
{
    constexpr int CO_M = 4, PIX_M = 4;
    constexpr int G    = CO_T / CO_M;
    constexpr int PTH  = 256 / G;
    constexpr int PIXB = PTH * PIX_M;
    constexpr int HW   = HOUT * WOUT;
    constexpr int NT   = 64 * HW;
    constexpr int PSZ  = HP * WP;
    static_assert(CIN / ZSPLIT == CI_T, "one smem weight tile per block");

    __shared__ __align__(16) float sw[CI_T * K * CO_T * 4];

    const int tco  = threadIdx.x % G;
    const int tpix = threadIdx.x / G;
    const int co0  = blockIdx.y * CO_T;
    const int nbase = blockIdx.x * PIXB;
    const int ci_begin = blockIdx.z * CI_T;

    // stage weights into [ci][kh][co][kw(4)] layout (kw padded to 4)
    {
        const int tot = CI_T * K * CO_T;
        for (int idx = threadIdx.x; idx < tot; idx += 256) {
            int ci = idx / (K * CO_T);
            int r  = idx % (K * CO_T);
            int kh = r / CO_T;
            int c  = r % CO_T;
            const float* src = w + ((long)(co0 + c) * CIN + (ci_begin + ci)) * (K * K) + kh * K;
            float4 v;
            v.x = src[0]; v.y = src[1]; v.z = src[2];
            v.w = (K == 4) ? src[3] : 0.f;
            *reinterpret_cast<float4*>(&sw[idx * 4]) = v;
        }
    }
    __syncthreads();

    int nidx[PIX_M];
    const float* pci[PIX_M];
    #pragma unroll
    for (int p = 0; p < PIX_M; p++) {
        int n = nbase + p * PTH + tpix;
        nidx[p] = n;
        int nn = (n < NT) ? n : 0;
        int b  = nn / HW;
        int hw = nn % HW;
        int ho = hw / WOUT, wo = hw % WOUT;
        pci[p] = in + ((long)b * CIN + ci_begin) * PSZ + (ho * S) * WP + (wo * S);
    }

    float acc[CO_M][PIX_M];
    #pragma unroll
    for (int m = 0; m < CO_M; m++)
        #pragma unroll
        for (int p = 0; p < PIX_M; p++) acc[m][p] = 0.f;

    #pragma unroll 2
    for (int ci = 0; ci < CI_T; ci++) {
        #pragma unroll
        for (int kh = 0; kh < K; kh++) {
            const float4* wbase = reinterpret_cast<const float4*>(
                &sw[((ci * K + kh) * CO_T + tco * CO_M) * 4]);
            float4 wv[CO_M];
            #pragma unroll
            for (int m = 0; m < CO_M; m++) wv[m] = wbase[m];

            if (K == 4) {
                // WP even and wo*S even -> 8B-aligned float2 loads
                float2 a01[PIX_M], a23[PIX_M];
                #pragma unroll
                for (int p = 0; p < PIX_M; p++) {
                    const float* q = pci[p] + kh * WP;
                    a01[p] = __ldg(reinterpret_cast<const float2*>(q));
                    a23[p] = __ldg(reinterpret_cast<const float2*>(q + 2));
                }
                #pragma unroll
                for (int m = 0; m < CO_M; m++)
                    #pragma unroll
                    for (int p = 0; p < PIX_M; p++) {
                        acc[m][p] = fmaf(wv[m].x, a01[p].x, acc[m][p]);
                        acc[m][p] = fmaf(wv[m].y, a01[p].y, acc[m][p]);
                        acc[m][p] = fmaf(wv[m].z, a23[p].x, acc[m][p]);
                        acc[m][p] = fmaf(wv[m].w, a23[p].y, acc[m][p]);
                    }
            } else {
                float a0[PIX_M], a1[PIX_M], a2[PIX_M];
                #pragma unroll
                for (int p = 0; p < PIX_M; p++) {
                    const float* q = pci[p] + kh * WP;
                    a0[p] = __ldg(q); a1[p] = __ldg(q + 1); a2[p] = __ldg(q + 2);
                }
                #pragma unroll
                for (int m = 0; m < CO_M; m++)
                    #pragma unroll
                    for (int p = 0; p < PIX_M; p++) {
                        acc[m][p] = fmaf(wv[m].x, a0[p], acc[m][p]);
                        acc[m][p] = fmaf(wv[m].y, a1[p], acc[m][p]);
                        acc[m][p] = fmaf(wv[m].z, a2[p], acc[m][p]);
                    }
            }
        }
        #pragma unroll
        for (int p = 0; p < PIX_M; p++) pci[p] += PSZ;
    }

    // epilogue (unpadded output layout)
    #pragma unroll
    for (int p = 0; p < PIX_M; p++) {
        int n = nidx[p];
        if (n >= NT) continue;
        int b = n / HW, hw = n % HW;
        #pragma unroll
        for (int m = 0; m < CO_M; m++) {
            int co = co0 + tco * CO_M + m;
            long oidx = ((long)b * COUT + co) * HW + hw;
            if (ATOMIC) {
                atomicAdd(out + oidx, acc[m][p]);
            } else {
                float v = acc[m][p] + (BIAS ? bias[co] : 0.f);
                if (RELU) v = fmaxf(v, 0.f);
                out[oidx] = v;
            }
        }
    }
}

// ---------------------------------------------------------------------------
// Instance norm: unpadded src -> PADDED dst (halo=0). One block per plane.
// ---------------------------------------------------------------------------
template<bool RELU>
__global__ void inorm_pad_kernel(const float* __restrict__ src, float* __restrict__ dst,
                                 int H, int W, int HP, int WP)
{
    const int HW = H * W;
    const float* s = src + (size_t)blockIdx.x * HW;
    float* d = dst + (size_t)blockIdx.x * HP * WP;

    float sum = 0.f, ssq = 0.f;
    for (int i = threadIdx.x; i < HW; i += blockDim.x) {
        float v = s[i];
        sum += v; ssq += v * v;
    }
    __shared__ float sh_s[256];
    __shared__ float sh_q[256];
    sh_s[threadIdx.x] = sum;
    sh_q[threadIdx.x] = ssq;
    __syncthreads();
    for (int off = blockDim.x >> 1; off > 0; off >>= 1) {
        if (threadIdx.x < off) {
            sh_s[threadIdx.x] += sh_s[threadIdx.x + off];
            sh_q[threadIdx.x] += sh_q[threadIdx.x + off];
        }
        __syncthreads();
    }
    float invN = 1.0f / (float)HW;
    float m = sh_s[0] * invN;
    float var = sh_q[0] * invN - m * m;
    float r = rsqrtf(var + 1e-5f);

    int tot = HP * WP;
    for (int i = threadIdx.x; i < tot; i += blockDim.x) {
        int h = i / WP, w = i % WP;
        bool in = (h >= 1) && (h <= H) && (w >= 1) && (w <= W);
        float v = 0.f;
        if (in) {
            v = (s[(h - 1) * W + (w - 1)] - m) * r;
            if (RELU) v = fmaxf(v, 0.f);
        }
        d[i] = v;
    }
}

// ---------------------------------------------------------------------------
// Tiny-plane inorm+pad: src 4x3 -> dst 6x6 padded (halo + extra right col = 0)
// One warp per plane; each lane handles i=lane and i=lane+32.
// ---------------------------------------------------------------------------
template<bool RELU>
__global__ void inorm_small_pad_kernel(const float* __restrict__ src,
                                       float* __restrict__ dst, int NPLANE)
{
    int warp = (blockIdx.x * blockDim.x + threadIdx.x) >> 5;
    int lane = threadIdx.x & 31;
    if (warp >= NPLANE) return;
    const float* s = src + (size_t)warp * 12;
    float* d = dst + (size_t)warp * 36;

    int h = lane / 6, w = lane % 6;
    bool interior = (h >= 1) && (h <= 4) && (w >= 1) && (w <= 3);
    float v = interior ? s[(h - 1) * 3 + (w - 1)] : 0.f;
    float sum = v, ssq = v * v;
    #pragma unroll
    for (int off = 16; off > 0; off >>= 1) {
        sum += __shfl_xor_sync(0xFFFFFFFFu, sum, off);
        ssq += __shfl_xor_sync(0xFFFFFFFFu, ssq, off);
    }
    float invN = 1.0f / 12.0f;
    float m = sum * invN;
    float var = ssq * invN - m * m;
    float r = rsqrtf(var + 1e-5f);
    float o = 0.f;
    if (interior) {
        o = (v - m) * r;
        if (RELU) o = fmaxf(o, 0.f);
    }
    d[lane] = o;
    if (lane < 4) d[lane + 32] = 0.f;   // i=32..35: h=5 row, never interior
}

// ---------------------------------------------------------------------------
// Maxpool on PADDED (6x6) planes of conv7 output -> flatten (64,512)
// ---------------------------------------------------------------------------
__global__ void maxpool_kernel(const float* __restrict__ in, float* __restrict__ out)
{
    int idx = blockIdx.x * blockDim.x + threadIdx.x;
    if (idx >= 64 * 256 * 2) return;
    int i = idx % 2;
    int c = (idx / 2) % 256;
    int b = idx / 512;
    const float* p = in + ((size_t)b * 256 + c) * 36;
    int r0 = (2 * i + 1) * 6 + 1;
    int r1 = (2 * i + 2) * 6 + 1;
    float v = fmaxf(fmaxf(p[r0], p[r0 + 1]), fmaxf(p[r1], p[r1 + 1]));
    out[(size_t)b * 512 + c * 2 + i] = v;
}

// ---------------------------------------------------------------------------
// FC1: (64,512) @ (128,512)^T + b, ReLU.
// ---------------------------------------------------------------------------
__global__ void fc1_kernel(const float* __restrict__ in,
                           const float* __restrict__ w,
                           const float* __restrict__ bias,
                           float* __restrict__ out)
{
    int b = blockIdx.x;
    int j = threadIdx.x;
    __shared__ float xs[512];
    for (int k = threadIdx.x; k < 512; k += 128) xs[k] = in[(size_t)b * 512 + k];
    __syncthreads();
    const float* wr = w + (size_t)j * 512;
    float acc = bias[j];
    #pragma unroll 8
    for (int k = 0; k < 512; k++)
        acc = fmaf(xs[k], __ldg(wr + k), acc);
    out[(size_t)b * 128 + j] = fmaxf(acc, 0.0f);
}

// ---------------------------------------------------------------------------
// FC2: (64,128) @ (50,128)^T + b, tanh -> d_out coor
// ---------------------------------------------------------------------------
__global__ void fc2_kernel(const float* __restrict__ in,
                           const float* __restrict__ w,
                           const float* __restrict__ bias,
                           float* __restrict__ out)
{
    int b = blockIdx.x;
    int j = threadIdx.x;
    if (j >= 50) return;
    const float* x  = in + (size_t)b * 128;
    const float* wr = w  + (size_t)j * 128;
    float acc = bias[j];
    #pragma unroll 8
    for (int k = 0; k < 128; k++)
        acc = fmaf(__ldg(x + k), __ldg(wr + k), acc);
    out[(size_t)b * 50 + j] = tanhf(acc);
}

// ---------------------------------------------------------------------------
// Loss kernel. Single block, 64 threads (thread = batch).
// ---------------------------------------------------------------------------
__global__ void loss_kernel(float* __restrict__ out)
{
    const float* pts = out;
    int b = threadIdx.x;
    const float* g = pts + (size_t)b * 50;
    #define G(i, j, comp) g[((i) * 5 + (j)) * 2 + (comp)]

    float rx = 0.f, ry = 0.f, cx = 0.f, cy = 0.f;
    for (int i = 0; i < 5; i++) {
        for (int s = 0; s < 3; s++) {
            #pragma unroll
            for (int comp = 0; comp < 2; comp++) {
                float a0 = G(i, s, comp), a1 = G(i, s + 1, comp), a2 = G(i, s + 2, comp);
                float d0 = (a1 - a0) * (a1 - a0);
                float d1 = (a2 - a1) * (a2 - a1);
                float rv = fmaxf(0.08f, fabsf(d1 - d0));
                if (comp == 0) rx += rv; else ry += rv;
                float c0 = G(s, i, comp), c1 = G(s + 1, i, comp), c2 = G(s + 2, i, comp);
                float e0 = (c1 - c0) * (c1 - c0);
                float e1 = (c2 - c1) * (c2 - c1);
                float cv = fmaxf(0.08f, fabsf(e1 - e0));
                if (comp == 0) cx += cv; else cy += cv;
            }
        }
    }

    __shared__ float sh[4][64];
    sh[0][b] = rx; sh[1][b] = ry; sh[2][b] = cx; sh[3][b] = cy;
    __syncthreads();
    for (int off = 32; off > 0; off >>= 1) {
        if (b < off) {
            sh[0][b] += sh[0][b + off];
            sh[1][b] += sh[1][b + off];
            sh[2][b] += sh[2][b + off];
            sh[3][b] += sh[3][b + off];
        }
        __syncthreads();
    }

    if (b == 0) {
        float inv = 1.0f / 960.0f;
        out[3200] = sh[0][0] * inv;
        out[3201] = sh[1][0] * inv;
        out[3202] = sh[2][0] * inv;
        out[3203] = sh[3][0] * inv;

        const float* g0 = pts;
        #define G0(i, j, comp) g0[((i) * 5 + (j)) * 2 + (comp)]
        float rg = 0.f, cg = 0.f;
        for (int i = 0; i < 5; i++) {
            for (int s = 0; s < 3; s++) {
                {
                    float x0 = G0(i, s, 0),     y0 = G0(i, s, 1);
                    float x1 = G0(i, s + 1, 0), y1 = G0(i, s + 1, 1);
                    float x2 = G0(i, s + 2, 0), y2 = G0(i, s + 2, 1);
                    rg += fabsf((y1 - y0) * (x1 - x2) - (y1 - y2) * (x1 - x0));
                }
                {
                    float x0 = G0(s, i, 0),     y0 = G0(s, i, 1);
                    float x1 = G0(s + 1, i, 0), y1 = G0(s + 1, i, 1);
                    float x2 = G0(s + 2, i, 0), y2 = G0(s + 2, i, 1);
                    cg += fabsf((y1 - y0) * (x1 - x2) - (y1 - y2) * (x1 - x0));
                }
            }
        }
        out[3204] = fmaxf(rg, 0.02f);
        out[3205] = fmaxf(cg, 0.02f);
    }
}

// ---------------------------------------------------------------------------
// Host-side orchestration
// ---------------------------------------------------------------------------
static inline int cdiv(int a, int b) { return (a + b - 1) / b; }

extern "C" void kernel_launch(void* const* d_in, const int* in_sizes, int n_in,
                              void* d_out, int out_size)
{
    (void)in_sizes; (void)n_in; (void)out_size;

    const float* x = (const float*)d_in[0];
    const float* W[8];
    const float* Bi[8];
    for (int i = 0; i < 8; i++) {
        W[i]  = (const float*)d_in[1 + 2 * i];
        Bi[i] = (const float*)d_in[2 + 2 * i];
    }
    const float* fc1_w = (const float*)d_in[17];
    const float* fc1_b = (const float*)d_in[18];
    const float* fc2_w = (const float*)d_in[19];
    const float* fc2_b = (const float*)d_in[20];
    float* out = (float*)d_out;

    float* X;  cudaGetSymbolAddress((void**)&X,  g_bufX);
    float* A;  cudaGetSymbolAddress((void**)&A,  g_bufA);
    float* Bb; cudaGetSymbolAddress((void**)&Bb, g_bufB);
    float* C;  cudaGetSymbolAddress((void**)&C,  g_bufC);

    // ---- pad input: x (64,5,256,192) -> X (64,5,258,194)
    pad_copy_kernel<<<64 * 5, 256>>>(x, X, 256, 192, 258, 194);

    // ---- L0: conv(X)->A [bias+relu], inorm A->B (padded 130x98)
    {
        dim3 grid(64 * 128 * 96 / 512, 1, 1);
        conv_tiled<4, 2, 5, 258, 194, 8, 128, 96, 8, 5, 1, false, true, true>
            <<<grid, 256>>>(X, W[0], Bi[0], A);
        inorm_pad_kernel<false><<<64 * 8, 256>>>(A, Bb, 128, 96, 130, 98);
    }
    // ---- L1: conv(B)->A, inorm A->C (padded 66x50)
    {
        dim3 grid(64 * 64 * 48 / 256, 1, 1);
        conv_tiled<4, 2, 8, 130, 98, 16, 64, 48, 16, 8, 1, false, false, false>
            <<<grid, 256>>>(Bb, W[1], nullptr, A);
        inorm_pad_kernel<true><<<64 * 16, 256>>>(A, C, 64, 48, 66, 50);
    }
    // ---- L2: conv(C)->A, inorm A->B (padded 34x26)
    {
        dim3 grid(64 * 32 * 24 / 256, 2, 1);
        conv_tiled<4, 2, 16, 66, 50, 32, 32, 24, 16, 16, 1, false, false, false>
            <<<grid, 256>>>(C, W[2], nullptr, A);
        inorm_pad_kernel<true><<<64 * 32, 256>>>(A, Bb, 32, 24, 34, 26);
    }
    // ---- L3: conv(B)->A (Z=2 atomic), inorm A->C (padded 18x14)
    {
        cudaMemsetAsync(A, 0, (size_t)64 * 64 * 16 * 12 * sizeof(float));
        dim3 grid(64 * 16 * 12 / 256, 4, 2);
        conv_tiled<4, 2, 32, 34, 26, 64, 16, 12, 16, 16, 2, true, false, false>
            <<<grid, 256>>>(Bb, W[3], nullptr, A);
        inorm_pad_kernel<true><<<64 * 64, 64>>>(A, C, 16, 12, 18, 14);
    }
    // ---- L4: conv(C)->A (Z=4 atomic), inorm A->B (padded 10x8)
    {
        cudaMemsetAsync(A, 0, (size_t)64 * 128 * 8 * 6 * sizeof(float));
        dim3 grid(64 * 8 * 6 / 256, 8, 4);
        conv_tiled<4, 2, 64, 18, 14, 128, 8, 6, 16, 16, 4, true, false, false>
            <<<grid, 256>>>(C, W[4], nullptr, A);
        inorm_pad_kernel<true><<<64 * 128, 64>>>(A, Bb, 8, 6, 10, 8);
    }
    // ---- L5: conv(B)->A (Z=8 atomic), inorm_small A->C (padded 6x6)
    {
        cudaMemsetAsync(A, 0, (size_t)64 * 256 * 4 * 3 * sizeof(float));
        dim3 grid(64 * 4 * 3 / 256, 16, 8);
        conv_tiled<4, 2, 128, 10, 8, 256, 4, 3, 16, 16, 8, true, false, false>
            <<<grid, 256>>>(Bb, W[5], nullptr, A);
        int np = 64 * 256;
        inorm_small_pad_kernel<true><<<cdiv(np * 32, 256), 256>>>(A, C, np);
    }
    // ---- L6: conv(C 6x6)->A (Z=16 atomic), inorm_small A->B (6x6)
    {
        cudaMemsetAsync(A, 0, (size_t)64 * 256 * 4 * 3 * sizeof(float));
        dim3 grid(64 * 4 * 3 / 256, 16, 16);
        conv_tiled<3, 1, 256, 6, 6, 256, 4, 3, 16, 16, 16, true, false, false>
            <<<grid, 256>>>(C, W[6], nullptr, A);
        int np = 64 * 256;
        inorm_small_pad_kernel<true><<<cdiv(np * 32, 256), 256>>>(A, Bb, np);
    }
    // ---- L7: conv(B 6x6)->A (Z=16 atomic), inorm_small A->C (6x6)
    {
        cudaMemsetAsync(A, 0, (size_t)64 * 256 * 4 * 3 * sizeof(float));
        dim3 grid(64 * 4 * 3 / 256, 16, 16);
        conv_tiled<3, 1, 256, 6, 6, 256, 4, 3, 16, 16, 16, true, false, false>
            <<<grid, 256>>>(Bb, W[7], nullptr, A);
        int np = 64 * 256;
        inorm_small_pad_kernel<true><<<cdiv(np * 32, 256), 256>>>(A, C, np);
    }

    // ---- maxpool (padded 6x6 C) -> B (64,512)
    maxpool_kernel<<<cdiv(64 * 256 * 2, 256), 256>>>(C, Bb);
    // ---- FC1: B -> A (64,128)
    fc1_kernel<<<64, 128>>>(Bb, fc1_w, fc1_b, A);
    // ---- FC2 + tanh: A -> out[0..3199]
    fc2_kernel<<<64, 64>>>(A, fc2_w, fc2_b, out);
    // ---- losses
    loss_kernel<<<1, 64>>>(out);
}

// round 5
// speedup vs baseline: 1.0885x; 1.0885x over previous
#include <cuda_runtime.h>
#include <math.h>

// ---------------------------------------------------------------------------
// Scratch buffers (device globals -- no allocation inside kernel_launch)
// ---------------------------------------------------------------------------
__device__ __align__(256) float g_bufX[16100000];   // padded input 64*5*258*194
__device__ __align__(256) float g_bufA[6400000];    // unpadded conv outputs
__device__ __align__(256) float g_bufB[6600000];    // padded activations
__device__ __align__(256) float g_bufC[6600000];    // padded activations

// ---------------------------------------------------------------------------
// Zero-pad copy: src (H x W planes) -> dst ((H+2) x (W+2), halo=0)
// ---------------------------------------------------------------------------
__global__ void pad_copy_kernel(const float* __restrict__ src, float* __restrict__ dst,
                                int H, int W, int HP, int WP)
{
    const float* s = src + (size_t)blockIdx.x * H * W;
    float* d = dst + (size_t)blockIdx.x * HP * WP;
    int tot = HP * WP;
    for (int i = threadIdx.x; i < tot; i += blockDim.x) {
        int h = i / WP, w = i % WP;
        bool in = (h >= 1) && (h <= H) && (w >= 1) && (w <= W);
        d[i] = in ? s[(h - 1) * W + (w - 1)] : 0.f;
    }
}

// ---------------------------------------------------------------------------
// Tiled implicit-GEMM conv on PADDED input (R3 scalar-load structure).
// Thread computes CO_M x PIX_M outputs; CO_M=8 for channel-heavy layers
// raises FFMA per memory instruction to ~2.7:1.
// ---------------------------------------------------------------------------
template<int K, int S, int CIN, int HP, int WP, int COUT, int HOUT, int WOUT,
         int CO_T, int CI_T, int CO_M, int ZSPLIT, bool ATOMIC, bool BIAS, bool RELU>
__global__ void __launch_bounds__(256)
conv_tiled(const float* __restrict__ in,
           const float* __restrict__ w,
           const float* __restrict__ bias,
           float* __restrict__ out)
{
    constexpr int PIX_M = 4;
    constexpr int G    = CO_T / CO_M;
    constexpr int PTH  = 256 / G;
    constexpr int PIXB = PTH * PIX_M;
    constexpr int KK   = K * K;
    constexpr int WPITCH = CI_T * KK + 1;
    constexpr int HW   = HOUT * WOUT;
    constexpr int NT   = 64 * HW;
    constexpr int PSZ  = HP * WP;
    static_assert(CIN / ZSPLIT == CI_T, "one smem weight tile per block");

    __shared__ float sw[CO_T * WPITCH];

    const int tco  = threadIdx.x % G;
    const int tpix = threadIdx.x / G;
    const int co0  = blockIdx.y * CO_T;
    const int nbase = blockIdx.x * PIXB;
    const int ci_begin = blockIdx.z * CI_T;

    // stage weights: [co][ci*KK] rows, padded pitch
    {
        const int tot = CO_T * CI_T * KK;
        const float* wsrc = w + ((long)co0 * CIN + ci_begin) * KK;
        for (int idx = threadIdx.x; idx < tot; idx += 256) {
            int c = idx / (CI_T * KK);
            int r = idx % (CI_T * KK);
            sw[c * WPITCH + r] = wsrc[(long)c * CIN * KK + r];
        }
    }
    __syncthreads();

    int nidx[PIX_M];
    const float* pci[PIX_M];
    #pragma unroll
    for (int p = 0; p < PIX_M; p++) {
        int n = nbase + p * PTH + tpix;
        nidx[p] = n;
        int nn = (n < NT) ? n : 0;
        int b  = nn / HW;
        int hw = nn % HW;
        int ho = hw / WOUT, wo = hw % WOUT;
        pci[p] = in + ((long)b * CIN + ci_begin) * PSZ + (ho * S) * WP + (wo * S);
    }

    float acc[CO_M][PIX_M];
    #pragma unroll
    for (int m = 0; m < CO_M; m++)
        #pragma unroll
        for (int p = 0; p < PIX_M; p++) acc[m][p] = 0.f;

    const float* wrow0 = &sw[(tco * CO_M) * WPITCH];
    for (int ci = 0; ci < CI_T; ci++) {
        const float* wrow = wrow0 + ci * KK;
        #pragma unroll
        for (int kh = 0; kh < K; kh++) {
            #pragma unroll
            for (int kw = 0; kw < K; kw++) {
                float iv[PIX_M];
                #pragma unroll
                for (int p = 0; p < PIX_M; p++)
                    iv[p] = __ldg(pci[p] + kh * WP + kw);
                float wv[CO_M];
                #pragma unroll
                for (int m = 0; m < CO_M; m++)
                    wv[m] = wrow[m * WPITCH + kh * K + kw];
                #pragma unroll
                for (int m = 0; m < CO_M; m++)
                    #pragma unroll
                    for (int p = 0; p < PIX_M; p++)
                        acc[m][p] = fmaf(wv[m], iv[p], acc[m][p]);
            }
        }
        #pragma unroll
        for (int p = 0; p < PIX_M; p++) pci[p] += PSZ;
    }

    // epilogue (unpadded output layout)
    #pragma unroll
    for (int p = 0; p < PIX_M; p++) {
        int n = nidx[p];
        if (n >= NT) continue;
        int b = n / HW, hw = n % HW;
        #pragma unroll
        for (int m = 0; m < CO_M; m++) {
            int co = co0 + tco * CO_M + m;
            long oidx = ((long)b * COUT + co) * HW + hw;
            if (ATOMIC) {
                atomicAdd(out + oidx, acc[m][p]);
            } else {
                float v = acc[m][p] + (BIAS ? bias[co] : 0.f);
                if (RELU) v = fmaxf(v, 0.f);
                out[oidx] = v;
            }
        }
    }
}

// ---------------------------------------------------------------------------
// Instance norm: unpadded src -> PADDED dst (halo=0). One block per plane.
// ---------------------------------------------------------------------------
template<bool RELU>
__global__ void inorm_pad_kernel(const float* __restrict__ src, float* __restrict__ dst,
                                 int H, int W, int HP, int WP)
{
    const int HW = H * W;
    const float* s = src + (size_t)blockIdx.x * HW;
    float* d = dst + (size_t)blockIdx.x * HP * WP;

    float sum = 0.f, ssq = 0.f;
    for (int i = threadIdx.x; i < HW; i += blockDim.x) {
        float v = s[i];
        sum += v; ssq += v * v;
    }
    __shared__ float sh_s[256];
    __shared__ float sh_q[256];
    sh_s[threadIdx.x] = sum;
    sh_q[threadIdx.x] = ssq;
    __syncthreads();
    for (int off = blockDim.x >> 1; off > 0; off >>= 1) {
        if (threadIdx.x < off) {
            sh_s[threadIdx.x] += sh_s[threadIdx.x + off];
            sh_q[threadIdx.x] += sh_q[threadIdx.x + off];
        }
        __syncthreads();
    }
    float invN = 1.0f / (float)HW;
    float m = sh_s[0] * invN;
    float var = sh_q[0] * invN - m * m;
    float r = rsqrtf(var + 1e-5f);

    int tot = HP * WP;
    for (int i = threadIdx.x; i < tot; i += blockDim.x) {
        int h = i / WP, w = i % WP;
        bool in = (h >= 1) && (h <= H) && (w >= 1) && (w <= W);
        float v = 0.f;
        if (in) {
            v = (s[(h - 1) * W + (w - 1)] - m) * r;
            if (RELU) v = fmaxf(v, 0.f);
        }
        d[i] = v;
    }
}

// ---------------------------------------------------------------------------
// Tiny-plane inorm+pad: src 4x3 -> dst 6x5 padded. One warp per plane.
// ---------------------------------------------------------------------------
template<bool RELU>
__global__ void inorm_small_pad_kernel(const float* __restrict__ src,
                                       float* __restrict__ dst, int NPLANE)
{
    int warp = (blockIdx.x * blockDim.x + threadIdx.x) >> 5;
    int lane = threadIdx.x & 31;
    if (warp >= NPLANE) return;
    const float* s = src + (size_t)warp * 12;
    float* d = dst + (size_t)warp * 30;

    int h = lane / 5, w = lane % 5;
    bool interior = (lane < 30) && (h >= 1) && (h <= 4) && (w >= 1) && (w <= 3);
    float v = interior ? s[(h - 1) * 3 + (w - 1)] : 0.f;
    float sum = v, ssq = v * v;
    #pragma unroll
    for (int off = 16; off > 0; off >>= 1) {
        sum += __shfl_xor_sync(0xFFFFFFFFu, sum, off);
        ssq += __shfl_xor_sync(0xFFFFFFFFu, ssq, off);
    }
    float invN = 1.0f / 12.0f;
    float m = sum * invN;
    float var = ssq * invN - m * m;
    float r = rsqrtf(var + 1e-5f);
    if (lane < 30) {
        float o = 0.f;
        if (interior) {
            o = (v - m) * r;
            if (RELU) o = fmaxf(o, 0.f);
        }
        d[lane] = o;
    }
}

// ---------------------------------------------------------------------------
// Maxpool on PADDED (6x5) planes of conv7 output -> flatten (64,512)
// ---------------------------------------------------------------------------
__global__ void maxpool_kernel(const float* __restrict__ in, float* __restrict__ out)
{
    int idx = blockIdx.x * blockDim.x + threadIdx.x;
    if (idx >= 64 * 256 * 2) return;
    int i = idx % 2;
    int c = (idx / 2) % 256;
    int b = idx / 512;
    const float* p = in + ((size_t)b * 256 + c) * 30;
    int r0 = (2 * i + 1) * 5 + 1;
    int r1 = (2 * i + 2) * 5 + 1;
    float v = fmaxf(fmaxf(p[r0], p[r0 + 1]), fmaxf(p[r1], p[r1 + 1]));
    out[(size_t)b * 512 + c * 2 + i] = v;
}

// ---------------------------------------------------------------------------
// FC1: (64,512) @ (128,512)^T + b, ReLU.
// ---------------------------------------------------------------------------
__global__ void fc1_kernel(const float* __restrict__ in,
                           const float* __restrict__ w,
                           const float* __restrict__ bias,
                           float* __restrict__ out)
{
    int b = blockIdx.x;
    int j = threadIdx.x;
    __shared__ float xs[512];
    for (int k = threadIdx.x; k < 512; k += 128) xs[k] = in[(size_t)b * 512 + k];
    __syncthreads();
    const float* wr = w + (size_t)j * 512;
    float acc = bias[j];
    #pragma unroll 8
    for (int k = 0; k < 512; k++)
        acc = fmaf(xs[k], __ldg(wr + k), acc);
    out[(size_t)b * 128 + j] = fmaxf(acc, 0.0f);
}

// ---------------------------------------------------------------------------
// FC2: (64,128) @ (50,128)^T + b, tanh -> d_out coor
// ---------------------------------------------------------------------------
__global__ void fc2_kernel(const float* __restrict__ in,
                           const float* __restrict__ w,
                           const float* __restrict__ bias,
                           float* __restrict__ out)
{
    int b = blockIdx.x;
    int j = threadIdx.x;
    if (j >= 50) return;
    const float* x  = in + (size_t)b * 128;
    const float* wr = w  + (size_t)j * 128;
    float acc = bias[j];
    #pragma unroll 8
    for (int k = 0; k < 128; k++)
        acc = fmaf(__ldg(x + k), __ldg(wr + k), acc);
    out[(size_t)b * 50 + j] = tanhf(acc);
}

// ---------------------------------------------------------------------------
// Loss kernel. Single block, 64 threads (thread = batch).
// ---------------------------------------------------------------------------
__global__ void loss_kernel(float* __restrict__ out)
{
    const float* pts = out;
    int b = threadIdx.x;
    const float* g = pts + (size_t)b * 50;
    #define G(i, j, comp) g[((i) * 5 + (j)) * 2 + (comp)]

    float rx = 0.f, ry = 0.f, cx = 0.f, cy = 0.f;
    for (int i = 0; i < 5; i++) {
        for (int s = 0; s < 3; s++) {
            #pragma unroll
            for (int comp = 0; comp < 2; comp++) {
                float a0 = G(i, s, comp), a1 = G(i, s + 1, comp), a2 = G(i, s + 2, comp);
                float d0 = (a1 - a0) * (a1 - a0);
                float d1 = (a2 - a1) * (a2 - a1);
                float rv = fmaxf(0.08f, fabsf(d1 - d0));
                if (comp == 0) rx += rv; else ry += rv;
                float c0 = G(s, i, comp), c1 = G(s + 1, i, comp), c2 = G(s + 2, i, comp);
                float e0 = (c1 - c0) * (c1 - c0);
                float e1 = (c2 - c1) * (c2 - c1);
                float cv = fmaxf(0.08f, fabsf(e1 - e0));
                if (comp == 0) cx += cv; else cy += cv;
            }
        }
    }

    __shared__ float sh[4][64];
    sh[0][b] = rx; sh[1][b] = ry; sh[2][b] = cx; sh[3][b] = cy;
    __syncthreads();
    for (int off = 32; off > 0; off >>= 1) {
        if (b < off) {
            sh[0][b] += sh[0][b + off];
            sh[1][b] += sh[1][b + off];
            sh[2][b] += sh[2][b + off];
            sh[3][b] += sh[3][b + off];
        }
        __syncthreads();
    }

    if (b == 0) {
        float inv = 1.0f / 960.0f;
        out[3200] = sh[0][0] * inv;
        out[3201] = sh[1][0] * inv;
        out[3202] = sh[2][0] * inv;
        out[3203] = sh[3][0] * inv;

        const float* g0 = pts;
        #define G0(i, j, comp) g0[((i) * 5 + (j)) * 2 + (comp)]
        float rg = 0.f, cg = 0.f;
        for (int i = 0; i < 5; i++) {
            for (int s = 0; s < 3; s++) {
                {
                    float x0 = G0(i, s, 0),     y0 = G0(i, s, 1);
                    float x1 = G0(i, s + 1, 0), y1 = G0(i, s + 1, 1);
                    float x2 = G0(i, s + 2, 0), y2 = G0(i, s + 2, 1);
                    rg += fabsf((y1 - y0) * (x1 - x2) - (y1 - y2) * (x1 - x0));
                }
                {
                    float x0 = G0(s, i, 0),     y0 = G0(s, i, 1);
                    float x1 = G0(s + 1, i, 0), y1 = G0(s + 1, i, 1);
                    float x2 = G0(s + 2, i, 0), y2 = G0(s + 2, i, 1);
                    cg += fabsf((y1 - y0) * (x1 - x2) - (y1 - y2) * (x1 - x0));
                }
            }
        }
        out[3204] = fmaxf(rg, 0.02f);
        out[3205] = fmaxf(cg, 0.02f);
    }
}

// ---------------------------------------------------------------------------
// Host-side orchestration
// ---------------------------------------------------------------------------
static inline int cdiv(int a, int b) { return (a + b - 1) / b; }

extern "C" void kernel_launch(void* const* d_in, const int* in_sizes, int n_in,
                              void* d_out, int out_size)
{
    (void)in_sizes; (void)n_in; (void)out_size;

    const float* x = (const float*)d_in[0];
    const float* W[8];
    const float* Bi[8];
    for (int i = 0; i < 8; i++) {
        W[i]  = (const float*)d_in[1 + 2 * i];
        Bi[i] = (const float*)d_in[2 + 2 * i];
    }
    const float* fc1_w = (const float*)d_in[17];
    const float* fc1_b = (const float*)d_in[18];
    const float* fc2_w = (const float*)d_in[19];
    const float* fc2_b = (const float*)d_in[20];
    float* out = (float*)d_out;

    float* X;  cudaGetSymbolAddress((void**)&X,  g_bufX);
    float* A;  cudaGetSymbolAddress((void**)&A,  g_bufA);
    float* Bb; cudaGetSymbolAddress((void**)&Bb, g_bufB);
    float* C;  cudaGetSymbolAddress((void**)&C,  g_bufC);

    // ---- pad input: x (64,5,256,192) -> X (64,5,258,194)
    pad_copy_kernel<<<64 * 5, 256>>>(x, X, 256, 192, 258, 194);

    // ---- L0: conv(X)->A [bias+relu], inorm A->B (padded 130x98)
    //      CO_M=4 (COUT=8): G=2, PTH=128, PIXB=512 -> 1536 blocks
    {
        dim3 grid(64 * 128 * 96 / 512, 1, 1);
        conv_tiled<4, 2, 5, 258, 194, 8, 128, 96, 8, 5, 4, 1, false, true, true>
            <<<grid, 256>>>(X, W[0], Bi[0], A);
        inorm_pad_kernel<false><<<64 * 8, 256>>>(A, Bb, 128, 96, 130, 98);
    }
    // ---- L1: CO_M=8, CO_T=16: G=2, PIXB=512 -> 384 blocks
    {
        dim3 grid(64 * 64 * 48 / 512, 1, 1);
        conv_tiled<4, 2, 8, 130, 98, 16, 64, 48, 16, 8, 8, 1, false, false, false>
            <<<grid, 256>>>(Bb, W[1], nullptr, A);
        inorm_pad_kernel<true><<<64 * 16, 256>>>(A, C, 64, 48, 66, 50);
    }
    // ---- L2: CO_M=8, CO_T=32: G=4, PIXB=256; Z=2 atomic -> 384 blocks
    {
        cudaMemsetAsync(A, 0, (size_t)64 * 32 * 32 * 24 * sizeof(float));
        dim3 grid(64 * 32 * 24 / 256, 1, 2);
        conv_tiled<4, 2, 16, 66, 50, 32, 32, 24, 32, 8, 8, 2, true, false, false>
            <<<grid, 256>>>(C, W[2], nullptr, A);
        inorm_pad_kernel<true><<<64 * 32, 256>>>(A, Bb, 32, 24, 34, 26);
    }
    // ---- L3: CO_T=32 (y=2), Z=4 -> 384 blocks
    {
        cudaMemsetAsync(A, 0, (size_t)64 * 64 * 16 * 12 * sizeof(float));
        dim3 grid(64 * 16 * 12 / 256, 2, 4);
        conv_tiled<4, 2, 32, 34, 26, 64, 16, 12, 32, 8, 8, 4, true, false, false>
            <<<grid, 256>>>(Bb, W[3], nullptr, A);
        inorm_pad_kernel<true><<<64 * 64, 64>>>(A, C, 16, 12, 18, 14);
    }
    // ---- L4: CO_T=32 (y=4), Z=8 -> 384 blocks
    {
        cudaMemsetAsync(A, 0, (size_t)64 * 128 * 8 * 6 * sizeof(float));
        dim3 grid(64 * 8 * 6 / 256, 4, 8);
        conv_tiled<4, 2, 64, 18, 14, 128, 8, 6, 32, 8, 8, 8, true, false, false>
            <<<grid, 256>>>(C, W[4], nullptr, A);
        inorm_pad_kernel<true><<<64 * 128, 64>>>(A, Bb, 8, 6, 10, 8);
    }
    // ---- L5: CO_T=32 (y=8), Z=16 -> 384 blocks
    {
        cudaMemsetAsync(A, 0, (size_t)64 * 256 * 4 * 3 * sizeof(float));
        dim3 grid(64 * 4 * 3 / 256 + 1, 8, 16);   // NT=768 -> x=3
        conv_tiled<4, 2, 128, 10, 8, 256, 4, 3, 32, 8, 8, 16, true, false, false>
            <<<dim3(3, 8, 16), 256>>>(Bb, W[5], nullptr, A);
        int np = 64 * 256;
        inorm_small_pad_kernel<true><<<cdiv(np * 32, 256), 256>>>(A, C, np);
    }
    // ---- L6: K=3 on padded 6x5; CO_T=32 (y=8), Z=16 (CI_T=16) -> 384 blocks
    {
        cudaMemsetAsync(A, 0, (size_t)64 * 256 * 4 * 3 * sizeof(float));
        conv_tiled<3, 1, 256, 6, 5, 256, 4, 3, 32, 16, 8, 16, true, false, false>
            <<<dim3(3, 8, 16), 256>>>(C, W[6], nullptr, A);
        int np = 64 * 256;
        inorm_small_pad_kernel<true><<<cdiv(np * 32, 256), 256>>>(A, Bb, np);
    }
    // ---- L7: same as L6
    {
        cudaMemsetAsync(A, 0, (size_t)64 * 256 * 4 * 3 * sizeof(float));
        conv_tiled<3, 1, 256, 6, 5, 256, 4, 3, 32, 16, 8, 16, true, false, false>
            <<<dim3(3, 8, 16), 256>>>(Bb, W[7], nullptr, A);
        int np = 64 * 256;
        inorm_small_pad_kernel<true><<<cdiv(np * 32, 256), 256>>>(A, C, np);
    }

    // ---- maxpool (padded 6x5 C) -> B (64,512)
    maxpool_kernel<<<cdiv(64 * 256 * 2, 256), 256>>>(C, Bb);
    // ---- FC1: B -> A (64,128)
    fc1_kernel<<<64, 128>>>(Bb, fc1_w, fc1_b, A);
    // ---- FC2 + tanh: A -> out[0..3199]
    fc2_kernel<<<64, 64>>>(A, fc2_w, fc2_b, out);
    // ---- losses
    loss_kernel<<<1, 64>>>(out);
}